// round 6
// baseline (speedup 1.0000x reference)
#include <cuda_runtime.h>

#define H 15
#define NPACK 541
// packed-weight layout (u64 {w,w} per weight), all values pre-scaled by 0.5
#define OW1 0      // 30
#define OB1 30     // 15
#define OW2 45     // 225
#define OB2 270    // 15
#define OW3 285    // 225
#define OB3 510    // 15
#define OW4 525    // 15
#define OB4 540    // 1

typedef unsigned long long u64;

__device__ u64 g_packed[NPACK];
__constant__ u64 cw[NPACK];

// ---- packed f32x2 helpers (sm_100+ PTX) ----
__device__ __forceinline__ u64 pk(float a, float b) {
    u64 r; asm("mov.b64 %0,{%1,%2};" : "=l"(r) : "f"(a), "f"(b)); return r;
}
__device__ __forceinline__ void upk(u64 v, float& a, float& b) {
    asm("mov.b64 {%0,%1},%2;" : "=f"(a), "=f"(b) : "l"(v));
}
__device__ __forceinline__ u64 fma2(u64 a, u64 b, u64 c) {
    u64 r; asm("fma.rn.f32x2 %0,%1,%2,%3;" : "=l"(r) : "l"(a), "l"(b), "l"(c)); return r;
}

// tanh on both lanes (1 MUFU each)
__device__ __forceinline__ u64 tanh2(u64 v) {
    float t0, t1; upk(v, t0, t1);
    float h0, h1;
    asm("tanh.approx.f32 %0,%1;" : "=f"(h0) : "f"(t0));
    asm("tanh.approx.f32 %0,%1;" : "=f"(h1) : "f"(t1));
    return pk(h0, h1);
}

// Weights are pre-scaled by 0.5, so each layer produces t = a/2 directly.
// SiLU(a) = a*sigmoid(a) = 2t * 0.5*(1+tanh t) = t + t*tanh(t) = fma2(t, tanh2(t), t)
__device__ __forceinline__ u64 silu2(u64 t) {
    return fma2(t, tanh2(t), t);
}

// Duplicate each scalar weight into a {0.5w, 0.5w} u64 pair.
__global__ void prep_kernel(const float* __restrict__ W1, const float* __restrict__ b1,
                            const float* __restrict__ W2, const float* __restrict__ b2,
                            const float* __restrict__ W3, const float* __restrict__ b3,
                            const float* __restrict__ W4, const float* __restrict__ b4) {
    int i = threadIdx.x;
    float v;
    if      (i < OB1) v = W1[i - OW1];
    else if (i < OW2) v = b1[i - OB1];
    else if (i < OB2) v = W2[i - OW2];
    else if (i < OW3) v = b2[i - OB2];
    else if (i < OB3) v = W3[i - OW3];
    else if (i < OW4) v = b3[i - OB3];
    else if (i < OB4) v = W4[i - OW4];
    else if (i == OB4) v = b4[0];
    else return;
    v *= 0.5f;   // tanh-form sigmoid pre-scale
    u64 p; asm("mov.b64 %0,{%1,%1};" : "=l"(p) : "f"(v));
    g_packed[i] = p;
}

// 2 rows per thread, all math packed f32x2, tanh-based SiLU.
__global__ __launch_bounds__(256) void mlp2_kernel(const float4* __restrict__ x,
                                                   float2* __restrict__ out,
                                                   int npair) {
    int i = blockIdx.x * blockDim.x + threadIdx.x;
    if (i >= npair) return;

    float4 xv = x[i];                  // {x0,y0,x1,y1} = rows 2i, 2i+1
    u64 xx = pk(xv.x, xv.z);
    u64 yy = pk(xv.y, xv.w);

    u64 h1[H], h2[H];

    // Layer 1: Linear(2,H)/2 -> SiLU
#pragma unroll
    for (int k = 0; k < H; k++) {
        u64 t = fma2(xx, cw[OW1 + k], fma2(yy, cw[OW1 + H + k], cw[OB1 + k]));
        h1[k] = silu2(t);
    }

    // Layer 2: Linear(H,H)/2 -> SiLU
#pragma unroll
    for (int k = 0; k < H; k++) {
        u64 t = cw[OB2 + k];
#pragma unroll
        for (int j = 0; j < H; j++) t = fma2(h1[j], cw[OW2 + j * H + k], t);
        h2[k] = silu2(t);
    }

    // Layer 3: Linear(H,H)/2 -> SiLU (reuse h1)
#pragma unroll
    for (int k = 0; k < H; k++) {
        u64 t = cw[OB3 + k];
#pragma unroll
        for (int j = 0; j < H; j++) t = fma2(h2[j], cw[OW3 + j * H + k], t);
        h1[k] = silu2(t);
    }

    // Layer 4: Linear(H,1)/2 -> Sigmoid = 0.5*tanh(t) + 0.5
    u64 t = cw[OB4];
#pragma unroll
    for (int j = 0; j < H; j++) t = fma2(h1[j], cw[OW4 + j], t);
    const u64 half2 = pk(0.5f, 0.5f);
    u64 s = fma2(tanh2(t), half2, half2);

    float s0, s1; upk(s, s0, s1);
    out[i] = make_float2(s0, s1);
}

extern "C" void kernel_launch(void* const* d_in, const int* in_sizes, int n_in,
                              void* d_out, int out_size) {
    // Inputs: x, W1, b1, W2, b2, W3, b3, W4, b4
    const float* x = (const float*)d_in[0];

    prep_kernel<<<1, 544>>>((const float*)d_in[1], (const float*)d_in[2],
                            (const float*)d_in[3], (const float*)d_in[4],
                            (const float*)d_in[5], (const float*)d_in[6],
                            (const float*)d_in[7], (const float*)d_in[8]);

    void* src = nullptr;
    cudaGetSymbolAddress(&src, g_packed);  // host-side query, capture-safe
    cudaMemcpyToSymbolAsync(cw, src, NPACK * sizeof(u64), 0,
                            cudaMemcpyDeviceToDevice, 0);

    int n = in_sizes[0] / 2;   // rows
    int npair = n / 2;         // 2 rows per thread
    int threads = 256;
    int blocks = (npair + threads - 1) / threads;
    mlp2_kernel<<<blocks, threads>>>((const float4*)x, (float2*)d_out, npair);
}

// round 7
// speedup vs baseline: 1.2312x; 1.2312x over previous
#include <cuda_runtime.h>

#define H 15
#define NPACK 541
// packed-weight layout (u64 {w,w} per weight)
// W1,b1 scaled by -log2(e); W2,W3,W4 unscaled; b2,b3,b4 scaled by -log2(e).
#define OW1 0      // 30
#define OB1 30     // 15
#define OW2 45     // 225
#define OB2 270    // 15
#define OW3 285    // 225
#define OB3 510    // 15
#define OW4 525    // 15
#define OB4 540    // 1

typedef unsigned long long u64;

__device__ u64 g_packed[NPACK];
__constant__ u64 cw[NPACK];

// ---- packed f32x2 helpers (sm_100+ PTX) ----
__device__ __forceinline__ u64 pk(float a, float b) {
    u64 r; asm("mov.b64 %0,{%1,%2};" : "=l"(r) : "f"(a), "f"(b)); return r;
}
__device__ __forceinline__ void upk(u64 v, float& a, float& b) {
    asm("mov.b64 {%0,%1},%2;" : "=f"(a), "=f"(b) : "l"(v));
}
__device__ __forceinline__ u64 fma2(u64 a, u64 b, u64 c) {
    u64 r; asm("fma.rn.f32x2 %0,%1,%2,%3;" : "=l"(r) : "l"(a), "l"(b), "l"(c)); return r;
}

// t = -log2e * a  (produced directly by the pre-scaled GEMV).
// g = t * rcp(1 + ex2(t)) = -log2e * SiLU(a); the -1/log2e compensation is
// folded into the NEXT layer's (linear) weights, which cancels to unscaled W.
__device__ __forceinline__ u64 act2(u64 t) {
    float t0, t1; upk(t, t0, t1);
    float e0, e1;
    asm("ex2.approx.f32 %0,%1;" : "=f"(e0) : "f"(t0));
    asm("ex2.approx.f32 %0,%1;" : "=f"(e1) : "f"(t1));
    float d0 = e0 + 1.0f, d1 = e1 + 1.0f;
    float r0, r1;
    asm("rcp.approx.f32 %0,%1;" : "=f"(r0) : "f"(d0));
    asm("rcp.approx.f32 %0,%1;" : "=f"(r1) : "f"(d1));
    return pk(t0 * r0, t1 * r1);
}

// final sigmoid on both lanes: sigma(a) = rcp(1 + ex2(t)), t = -log2e*a
__device__ __forceinline__ u64 sig2(u64 t) {
    float t0, t1; upk(t, t0, t1);
    float e0, e1;
    asm("ex2.approx.f32 %0,%1;" : "=f"(e0) : "f"(t0));
    asm("ex2.approx.f32 %0,%1;" : "=f"(e1) : "f"(t1));
    float d0 = e0 + 1.0f, d1 = e1 + 1.0f;
    float r0, r1;
    asm("rcp.approx.f32 %0,%1;" : "=f"(r0) : "f"(d0));
    asm("rcp.approx.f32 %0,%1;" : "=f"(r1) : "f"(d1));
    return pk(r0, r1);
}

#define NLOG2E (-1.4426950408889634f)

// Duplicate each scalar weight into a {w',w'} u64 pair with t-space scaling.
__global__ void prep_kernel(const float* __restrict__ W1, const float* __restrict__ b1,
                            const float* __restrict__ W2, const float* __restrict__ b2,
                            const float* __restrict__ W3, const float* __restrict__ b3,
                            const float* __restrict__ W4, const float* __restrict__ b4) {
    int i = threadIdx.x;
    float v;
    if      (i < OB1) v = W1[i - OW1] * NLOG2E;   // W1 scaled
    else if (i < OW2) v = b1[i - OB1] * NLOG2E;   // b1 scaled
    else if (i < OB2) v = W2[i - OW2];            // W2 unscaled
    else if (i < OW3) v = b2[i - OB2] * NLOG2E;   // b2 scaled
    else if (i < OB3) v = W3[i - OW3];            // W3 unscaled
    else if (i < OW4) v = b3[i - OB3] * NLOG2E;   // b3 scaled
    else if (i < OB4) v = W4[i - OW4];            // W4 unscaled
    else if (i == OB4) v = b4[0] * NLOG2E;        // b4 scaled
    else return;
    u64 p; asm("mov.b64 %0,{%1,%1};" : "=l"(p) : "f"(v));
    g_packed[i] = p;
}

// 4 rows per thread: two packed f32x2 pipelines (a = pair i, b = pair i+nthread)
// sharing every weight load (one LDCU.64 feeds two FFMA2).
__global__ __launch_bounds__(128) void mlp4_kernel(const float4* __restrict__ x,
                                                   float2* __restrict__ out,
                                                   int nthread) {
    int i = blockIdx.x * blockDim.x + threadIdx.x;
    if (i >= nthread) return;
    int ib = i + nthread;

    float4 xa = x[i];                  // rows of pair i
    float4 xb = x[ib];                 // rows of pair i+nthread
    u64 xxa = pk(xa.x, xa.z), yya = pk(xa.y, xa.w);
    u64 xxb = pk(xb.x, xb.z), yyb = pk(xb.y, xb.w);

    u64 h1a[H], h1b[H], h2a[H], h2b[H];

    // Layer 1
#pragma unroll
    for (int k = 0; k < H; k++) {
        u64 w0 = cw[OW1 + k], w1 = cw[OW1 + H + k], b = cw[OB1 + k];
        h1a[k] = act2(fma2(xxa, w0, fma2(yya, w1, b)));
        h1b[k] = act2(fma2(xxb, w0, fma2(yyb, w1, b)));
    }

    // Layer 2
#pragma unroll
    for (int k = 0; k < H; k++) {
        u64 ta = cw[OB2 + k], tb = ta;
#pragma unroll
        for (int j = 0; j < H; j++) {
            u64 w = cw[OW2 + j * H + k];
            ta = fma2(h1a[j], w, ta);
            tb = fma2(h1b[j], w, tb);
        }
        h2a[k] = act2(ta);
        h2b[k] = act2(tb);
    }

    // Layer 3 (reuse h1)
#pragma unroll
    for (int k = 0; k < H; k++) {
        u64 ta = cw[OB3 + k], tb = ta;
#pragma unroll
        for (int j = 0; j < H; j++) {
            u64 w = cw[OW3 + j * H + k];
            ta = fma2(h2a[j], w, ta);
            tb = fma2(h2b[j], w, tb);
        }
        h1a[k] = act2(ta);
        h1b[k] = act2(tb);
    }

    // Layer 4 + sigmoid
    u64 ta = cw[OB4], tb = ta;
#pragma unroll
    for (int j = 0; j < H; j++) {
        u64 w = cw[OW4 + j];
        ta = fma2(h1a[j], w, ta);
        tb = fma2(h1b[j], w, tb);
    }
    u64 sa = sig2(ta), sb = sig2(tb);

    float s0, s1;
    upk(sa, s0, s1); out[i]  = make_float2(s0, s1);
    upk(sb, s0, s1); out[ib] = make_float2(s0, s1);
}

extern "C" void kernel_launch(void* const* d_in, const int* in_sizes, int n_in,
                              void* d_out, int out_size) {
    // Inputs: x, W1, b1, W2, b2, W3, b3, W4, b4
    const float* x = (const float*)d_in[0];

    prep_kernel<<<1, 544>>>((const float*)d_in[1], (const float*)d_in[2],
                            (const float*)d_in[3], (const float*)d_in[4],
                            (const float*)d_in[5], (const float*)d_in[6],
                            (const float*)d_in[7], (const float*)d_in[8]);

    void* src = nullptr;
    cudaGetSymbolAddress(&src, g_packed);  // host-side query, capture-safe
    cudaMemcpyToSymbolAsync(cw, src, NPACK * sizeof(u64), 0,
                            cudaMemcpyDeviceToDevice, 0);

    int n = in_sizes[0] / 2;     // rows
    int npair = n / 2;           // float4 pairs
    int nthread = npair / 2;     // 2 pairs (4 rows) per thread
    int threads = 128;
    int blocks = (nthread + threads - 1) / threads;
    mlp4_kernel<<<blocks, threads>>>((const float4*)x, (float2*)d_out, nthread);
}